// round 6
// baseline (speedup 1.0000x reference)
#include <cuda_runtime.h>

#define TS 64
#define TP 65   // padded smem row stride (bank-conflict mitigation for transposed reads)
#define SVAL 2.1972245773362196f   // log(9)

// Scratch (device globals -- no allocation allowed). Sized for B=8, L=1024.
__device__ float g_uu[8 * 1024 * 1024];
__device__ float g_ah[8 * 1024 * 1024];
__device__ float g_rspart[8 * 1024 * 16];   // per-(row, column-tile) partial rowsums
__device__ float g_g[8 * 1024];             // lmbd_i * soft_sign(rowsum_i - 1)
__device__ float g_lmbd[8 * 1024];

__device__ __forceinline__ float sigf(float v) { return 1.0f / (1.0f + __expf(-v)); }

// m_ij from x rows p=(ba,bu,bc,bg)_i, q=(ba,bu,bc,bg)_j  (symmetric)
__device__ __forceinline__ float mfun(float p0, float p1, float p2, float p3,
                                      float q0, float q1, float q2, float q3) {
    return p0 * q1 + q0 * p1 + p2 * q3 + q2 * p3 + p1 * q3 + q1 * p3;
}

// 3 -> 3 -> 1 MLP, relu on both layers
__device__ __forceinline__ float mlp3(const float* w1, const float* b1,
                                      const float* w2, float b2,
                                      float f0, float f1, float f2) {
    float h0 = fmaxf(fmaf(w1[0], f0, fmaf(w1[1], f1, fmaf(w1[2], f2, b1[0]))), 0.f);
    float h1 = fmaxf(fmaf(w1[3], f0, fmaf(w1[4], f1, fmaf(w1[5], f2, b1[1]))), 0.f);
    float h2 = fmaxf(fmaf(w1[6], f0, fmaf(w1[7], f1, fmaf(w1[8], f2, b1[2]))), 0.f);
    return fmaxf(fmaf(w2[0], h0, fmaf(w2[1], h1, fmaf(w2[2], h2, b2))), 0.f);
}

__device__ __forceinline__ void u2uah(float uq, float& uu, float& ah) {
    uu = sigf(2.f * (uq - SVAL)) * uq;
    ah = sigf(uu) * sigf(2.f * (uu - SVAL));
}

__device__ __forceinline__ void decode_pair(int p, int nt, int& I, int& J) {
    int rem = p, rl = nt, i = 0;
    while (rem >= rl) { rem -= rl; rl--; i++; }
    I = i; J = i + rem;
}

// ---------------------------------------------------------------------------
// Init: uu = ss(u-S)*u ; a_hat = sig(uu)*ss(uu-S) ; partial rowsums of a0
// ---------------------------------------------------------------------------
__global__ void __launch_bounds__(256) init_kernel(
    const float* __restrict__ u, const float* __restrict__ x,
    int B, int L, int nt) {
    __shared__ float H1[TS * TP];
    __shared__ float H2[TS * TP];
    __shared__ float xs[2][4][TS];

    int I, J;
    decode_pair(blockIdx.x, nt, I, J);
    int b = blockIdx.y;
    bool diag = (I == J);
    int i0 = I * TS, j0 = J * TS;
    int tid = threadIdx.x, tx = tid & 15, ty = tid >> 4;
    size_t MN = (size_t)L * L;
    const float* Ub = u + (size_t)b * MN;
    float* uuB = g_uu + (size_t)b * MN;
    float* ahB = g_ah + (size_t)b * MN;

    if (tid < TS) {
        const float* xr = x + ((size_t)b * L + i0 + tid) * 4;
        xs[0][0][tid] = xr[0]; xs[0][1][tid] = xr[1]; xs[0][2][tid] = xr[2]; xs[0][3][tid] = xr[3];
        xr = x + ((size_t)b * L + j0 + tid) * 4;
        xs[1][0][tid] = xr[0]; xs[1][1][tid] = xr[1]; xs[1][2][tid] = xr[2]; xs[1][3][tid] = xr[3];
    }

#pragma unroll
    for (int it = 0; it < 4; it++) {
        int r = ty + 16 * it, c0 = 4 * tx;
        size_t off = (size_t)(i0 + r) * L + j0 + c0;
        float4 uv = *(const float4*)(Ub + off);
        float4 uo, ao;
        u2uah(uv.x, uo.x, ao.x); u2uah(uv.y, uo.y, ao.y);
        u2uah(uv.z, uo.z, ao.z); u2uah(uv.w, uo.w, ao.w);
        *(float4*)(uuB + off) = uo;
        *(float4*)(ahB + off) = ao;
        H1[r * TP + c0] = ao.x; H1[r * TP + c0 + 1] = ao.y;
        H1[r * TP + c0 + 2] = ao.z; H1[r * TP + c0 + 3] = ao.w;
        if (!diag) {
            size_t off2 = (size_t)(j0 + r) * L + i0 + c0;
            float4 uv2 = *(const float4*)(Ub + off2);
            float4 uo2, ao2;
            u2uah(uv2.x, uo2.x, ao2.x); u2uah(uv2.y, uo2.y, ao2.y);
            u2uah(uv2.z, uo2.z, ao2.z); u2uah(uv2.w, uo2.w, ao2.w);
            *(float4*)(uuB + off2) = uo2;
            *(float4*)(ahB + off2) = ao2;
            H2[r * TP + c0] = ao2.x; H2[r * TP + c0 + 1] = ao2.y;
            H2[r * TP + c0 + 2] = ao2.z; H2[r * TP + c0 + 3] = ao2.w;
        }
    }
    __syncthreads();

#pragma unroll
    for (int it = 0; it < 4; it++) {
        int r = ty + 16 * it, c0 = 4 * tx;
        {
            float p0 = xs[0][0][r], p1 = xs[0][1][r], p2 = xs[0][2][r], p3 = xs[0][3][r];
            float part = 0.f;
#pragma unroll
            for (int k = 0; k < 4; k++) {
                int c = c0 + k;
                float q0 = xs[1][0][c], q1 = xs[1][1][c], q2 = xs[1][2][c], q3 = xs[1][3][c];
                float mm = mfun(p0, p1, p2, p3, q0, q1, q2, q3);
                float h1 = H1[r * TP + c];
                float h2 = diag ? H1[c * TP + r] : H2[c * TP + r];
                part += 0.5f * (h1 * h1 + h2 * h2) * mm;
            }
            part += __shfl_xor_sync(0xffffffffu, part, 8, 16);
            part += __shfl_xor_sync(0xffffffffu, part, 4, 16);
            part += __shfl_xor_sync(0xffffffffu, part, 2, 16);
            part += __shfl_xor_sync(0xffffffffu, part, 1, 16);
            if (tx == 0) g_rspart[((size_t)(b * L + i0 + r)) * nt + J] = part;
        }
        if (!diag) {
            float p0 = xs[1][0][r], p1 = xs[1][1][r], p2 = xs[1][2][r], p3 = xs[1][3][r];
            float part = 0.f;
#pragma unroll
            for (int k = 0; k < 4; k++) {
                int c = c0 + k;
                float q0 = xs[0][0][c], q1 = xs[0][1][c], q2 = xs[0][2][c], q3 = xs[0][3][c];
                float mm = mfun(p0, p1, p2, p3, q0, q1, q2, q3);
                float h1 = H2[r * TP + c];
                float h2 = H1[c * TP + r];
                part += 0.5f * (h1 * h1 + h2 * h2) * mm;
            }
            part += __shfl_xor_sync(0xffffffffu, part, 8, 16);
            part += __shfl_xor_sync(0xffffffffu, part, 4, 16);
            part += __shfl_xor_sync(0xffffffffu, part, 2, 16);
            part += __shfl_xor_sync(0xffffffffu, part, 1, 16);
            if (tx == 0) g_rspart[((size_t)(b * L + j0 + r)) * nt + I] = part;
        }
    }
}

// ---------------------------------------------------------------------------
// lmbd0 = relu(rowsum - 1) (W_PEN=1); g = lmbd * ss(rowsum - 1)
// ---------------------------------------------------------------------------
__global__ void lmbd_init_kernel(int BL, int nt) {
    int i = blockIdx.x * blockDim.x + threadIdx.x;
    if (i >= BL) return;
    float rs = 0.f;
    const float* rp = g_rspart + (size_t)i * nt;
    for (int k = 0; k < nt; k++) rs += rp[k];
    float lm = fmaxf(rs - 1.f, 0.f);
    g_lmbd[i] = lm;
    g_g[i] = lm * sigf(2.f * (rs - 1.f));
}

// ---------------------------------------------------------------------------
// One timestep over a tile pair: ah_new + a (out[t]) + partial rowsums of a
// ---------------------------------------------------------------------------
__global__ void __launch_bounds__(256, 2) step_kernel(
    const float* __restrict__ x,
    const float* __restrict__ aW1, const float* __restrict__ ab1,
    const float* __restrict__ aW2, const float* __restrict__ ab2,
    const float* __restrict__ rW1, const float* __restrict__ rb1,
    const float* __restrict__ rW2, const float* __restrict__ rb2,
    float* __restrict__ out, int t, int B, int L, int nt) {
    extern __shared__ float sm[];
    float* U1 = sm;
    float* U2 = sm + TS * TP;
    float* N1 = sm + 2 * TS * TP;
    float* N2 = sm + 3 * TS * TP;
    __shared__ float xs[2][4][TS];
    __shared__ float gsm[2][TS];

    int I, J;
    decode_pair(blockIdx.x, nt, I, J);
    int b = blockIdx.y;
    bool diag = (I == J);
    int i0 = I * TS, j0 = J * TS;
    int tid = threadIdx.x, tx = tid & 15, ty = tid >> 4;
    size_t MN = (size_t)L * L;
    const float* uuB = g_uu + (size_t)b * MN;
    float* ahB = g_ah + (size_t)b * MN;
    float* outB = out + (size_t)b * MN;

    if (tid < TS) {
        const float* xr = x + ((size_t)b * L + i0 + tid) * 4;
        xs[0][0][tid] = xr[0]; xs[0][1][tid] = xr[1]; xs[0][2][tid] = xr[2]; xs[0][3][tid] = xr[3];
        xr = x + ((size_t)b * L + j0 + tid) * 4;
        xs[1][0][tid] = xr[0]; xs[1][1][tid] = xr[1]; xs[1][2][tid] = xr[2]; xs[1][3][tid] = xr[3];
        gsm[0][tid] = g_g[b * L + i0 + tid];
        gsm[1][tid] = g_g[b * L + j0 + tid];
    }

    // per-timestep MLP params -> registers (uniform broadcast loads)
    float w1a[9], b1a[3], w2a[3], b2a, w1r[9], b1r[3], w2r[3], b2r;
    {
        const float* q1 = aW1 + t * 9; const float* q2 = rW1 + t * 9;
#pragma unroll
        for (int k = 0; k < 9; k++) { w1a[k] = __ldg(q1 + k); w1r[k] = __ldg(q2 + k); }
        const float* q3 = ab1 + t * 3; const float* q4 = rb1 + t * 3;
        const float* q5 = aW2 + t * 3; const float* q6 = rW2 + t * 3;
#pragma unroll
        for (int k = 0; k < 3; k++) {
            b1a[k] = __ldg(q3 + k); b1r[k] = __ldg(q4 + k);
            w2a[k] = __ldg(q5 + k); w2r[k] = __ldg(q6 + k);
        }
        b2a = __ldg(ab2 + t); b2r = __ldg(rb2 + t);
    }

    // ---- Phase A: stage uu tiles in smem ----
#pragma unroll
    for (int it = 0; it < 4; it++) {
        int r = ty + 16 * it, c0 = 4 * tx;
        float4 v = *(const float4*)(uuB + (size_t)(i0 + r) * L + j0 + c0);
        U1[r * TP + c0] = v.x; U1[r * TP + c0 + 1] = v.y;
        U1[r * TP + c0 + 2] = v.z; U1[r * TP + c0 + 3] = v.w;
        if (!diag) {
            float4 v2 = *(const float4*)(uuB + (size_t)(j0 + r) * L + i0 + c0);
            U2[r * TP + c0] = v2.x; U2[r * TP + c0 + 1] = v2.y;
            U2[r * TP + c0 + 2] = v2.z; U2[r * TP + c0 + 3] = v2.w;
        }
    }
    __syncthreads();

    // ---- Phase B: grad, MLPs, ah_new (in-place global update + smem N) ----
#pragma unroll
    for (int it = 0; it < 4; it++) {
        int r = ty + 16 * it, c0 = 4 * tx;
        {
            size_t off = (size_t)(i0 + r) * L + j0 + c0;
            float4 ahv = *(const float4*)(ahB + off);
            float ahs[4] = {ahv.x, ahv.y, ahv.z, ahv.w};
            float gi = gsm[0][r];
            float p0 = xs[0][0][r], p1 = xs[0][1][r], p2 = xs[0][2][r], p3 = xs[0][3][r];
            float nv[4];
#pragma unroll
            for (int k = 0; k < 4; k++) {
                int c = c0 + k;
                float ah = ahs[k];
                float uuv = U1[r * TP + c];
                float uut = diag ? U1[c * TP + r] : U2[c * TP + r];
                float gj = gsm[1][c];
                float q0 = xs[1][0][c], q1 = xs[1][1][c], q2 = xs[1][2][c], q3 = xs[1][3][c];
                float mm = mfun(p0, p1, p2, p3, q0, q1, q2, q3);
                float gs = -0.5f * (uuv + uut) + gi + gj;
                float grad = ah * mm * gs;
                float oA = mlp3(w1a, b1a, w2a, b2a, ah, grad, uuv);
                float rho = mlp3(w1r, b1r, w2r, b2r, ah, grad, uuv);
                float ahn = fminf(fmaxf(fabsf(oA) - rho, 0.f), 1.f);
                N1[r * TP + c] = ahn;
                nv[k] = ahn;
            }
            *(float4*)(ahB + off) = make_float4(nv[0], nv[1], nv[2], nv[3]);
        }
        if (!diag) {
            size_t off = (size_t)(j0 + r) * L + i0 + c0;
            float4 ahv = *(const float4*)(ahB + off);
            float ahs[4] = {ahv.x, ahv.y, ahv.z, ahv.w};
            float gi = gsm[1][r];
            float p0 = xs[1][0][r], p1 = xs[1][1][r], p2 = xs[1][2][r], p3 = xs[1][3][r];
            float nv[4];
#pragma unroll
            for (int k = 0; k < 4; k++) {
                int c = c0 + k;
                float ah = ahs[k];
                float uuv = U2[r * TP + c];
                float uut = U1[c * TP + r];
                float gj = gsm[0][c];
                float q0 = xs[0][0][c], q1 = xs[0][1][c], q2 = xs[0][2][c], q3 = xs[0][3][c];
                float mm = mfun(p0, p1, p2, p3, q0, q1, q2, q3);
                float gs = -0.5f * (uuv + uut) + gi + gj;
                float grad = ah * mm * gs;
                float oA = mlp3(w1a, b1a, w2a, b2a, ah, grad, uuv);
                float rho = mlp3(w1r, b1r, w2r, b2r, ah, grad, uuv);
                float ahn = fminf(fmaxf(fabsf(oA) - rho, 0.f), 1.f);
                N2[r * TP + c] = ahn;
                nv[k] = ahn;
            }
            *(float4*)(ahB + off) = make_float4(nv[0], nv[1], nv[2], nv[3]);
        }
    }
    __syncthreads();

    // ---- Phase C: a = contact(ah_new), write out[t], partial rowsums ----
#pragma unroll
    for (int it = 0; it < 4; it++) {
        int r = ty + 16 * it, c0 = 4 * tx;
        {
            float p0 = xs[0][0][r], p1 = xs[0][1][r], p2 = xs[0][2][r], p3 = xs[0][3][r];
            float av[4]; float part = 0.f;
#pragma unroll
            for (int k = 0; k < 4; k++) {
                int c = c0 + k;
                float q0 = xs[1][0][c], q1 = xs[1][1][c], q2 = xs[1][2][c], q3 = xs[1][3][c];
                float mm = mfun(p0, p1, p2, p3, q0, q1, q2, q3);
                float n1 = N1[r * TP + c];
                float n2 = diag ? N1[c * TP + r] : N2[c * TP + r];
                float a = 0.5f * (n1 * n1 + n2 * n2) * mm;
                av[k] = a; part += a;
            }
            *(float4*)(outB + (size_t)(i0 + r) * L + j0 + c0) =
                make_float4(av[0], av[1], av[2], av[3]);
            part += __shfl_xor_sync(0xffffffffu, part, 8, 16);
            part += __shfl_xor_sync(0xffffffffu, part, 4, 16);
            part += __shfl_xor_sync(0xffffffffu, part, 2, 16);
            part += __shfl_xor_sync(0xffffffffu, part, 1, 16);
            if (tx == 0) g_rspart[((size_t)(b * L + i0 + r)) * nt + J] = part;
        }
        if (!diag) {
            float p0 = xs[1][0][r], p1 = xs[1][1][r], p2 = xs[1][2][r], p3 = xs[1][3][r];
            float av[4]; float part = 0.f;
#pragma unroll
            for (int k = 0; k < 4; k++) {
                int c = c0 + k;
                float q0 = xs[0][0][c], q1 = xs[0][1][c], q2 = xs[0][2][c], q3 = xs[0][3][c];
                float mm = mfun(p0, p1, p2, p3, q0, q1, q2, q3);
                float n1 = N2[r * TP + c];
                float n2 = N1[c * TP + r];
                float a = 0.5f * (n1 * n1 + n2 * n2) * mm;
                av[k] = a; part += a;
            }
            *(float4*)(outB + (size_t)(j0 + r) * L + i0 + c0) =
                make_float4(av[0], av[1], av[2], av[3]);
            part += __shfl_xor_sync(0xffffffffu, part, 8, 16);
            part += __shfl_xor_sync(0xffffffffu, part, 4, 16);
            part += __shfl_xor_sync(0xffffffffu, part, 2, 16);
            part += __shfl_xor_sync(0xffffffffu, part, 1, 16);
            if (tx == 0) g_rspart[((size_t)(b * L + j0 + r)) * nt + I] = part;
        }
    }
}

// ---------------------------------------------------------------------------
// lmbd update: lg = relu(rowsum-1); lmbd = mlp2([lmbd, lg]); g = lmbd*ss(rs-1)
// ---------------------------------------------------------------------------
__global__ void lmbd_step_kernel(int BL, int nt,
    const float* __restrict__ lW1, const float* __restrict__ lb1,
    const float* __restrict__ lW2, const float* __restrict__ lb2, int t) {
    int i = blockIdx.x * blockDim.x + threadIdx.x;
    if (i >= BL) return;
    float rs = 0.f;
    const float* rp = g_rspart + (size_t)i * nt;
    for (int k = 0; k < nt; k++) rs += rp[k];
    float lg = fmaxf(rs - 1.f, 0.f);
    float lm = g_lmbd[i];
    const float* w1 = lW1 + t * 6;
    const float* b1 = lb1 + t * 3;
    const float* w2 = lW2 + t * 3;
    float b2 = __ldg(lb2 + t);
    float h0 = fmaxf(__ldg(w1 + 0) * lm + __ldg(w1 + 1) * lg + __ldg(b1 + 0), 0.f);
    float h1 = fmaxf(__ldg(w1 + 2) * lm + __ldg(w1 + 3) * lg + __ldg(b1 + 1), 0.f);
    float h2 = fmaxf(__ldg(w1 + 4) * lm + __ldg(w1 + 5) * lg + __ldg(b1 + 2), 0.f);
    float o = fmaxf(__ldg(w2 + 0) * h0 + __ldg(w2 + 1) * h1 + __ldg(w2 + 2) * h2 + b2, 0.f);
    g_lmbd[i] = o;
    g_g[i] = o * sigf(2.f * (rs - 1.f));
}

// ---------------------------------------------------------------------------
extern "C" void kernel_launch(void* const* d_in, const int* in_sizes, int n_in,
                              void* d_out, int out_size) {
    const float* u   = (const float*)d_in[0];
    const float* x   = (const float*)d_in[1];
    const float* aW1 = (const float*)d_in[3];
    const float* ab1 = (const float*)d_in[4];
    const float* aW2 = (const float*)d_in[5];
    const float* ab2 = (const float*)d_in[6];
    const float* rW1 = (const float*)d_in[7];
    const float* rb1 = (const float*)d_in[8];
    const float* rW2 = (const float*)d_in[9];
    const float* rb2 = (const float*)d_in[10];
    const float* lW1 = (const float*)d_in[11];
    const float* lb1 = (const float*)d_in[12];
    const float* lW2 = (const float*)d_in[13];
    const float* lb2 = (const float*)d_in[14];

    long long BLL = in_sizes[0];            // B*L*L
    long long BL4 = in_sizes[1];            // B*L*4
    int L = (int)(BLL * 4 / BL4);           // L = (B*L*L*4)/(B*L*4)
    int B = (int)(BL4 / (4LL * L));
    int T = (int)((long long)out_size / BLL);
    int nt = L / TS;
    int npairs = nt * (nt + 1) / 2;
    int BL = B * L;

    const int smem_bytes = 4 * TS * TP * (int)sizeof(float);   // 66,560 B
    cudaFuncSetAttribute(step_kernel,
                         cudaFuncAttributeMaxDynamicSharedMemorySize, smem_bytes);

    dim3 grid(npairs, B);
    init_kernel<<<grid, 256>>>(u, x, B, L, nt);
    lmbd_init_kernel<<<(BL + 255) / 256, 256>>>(BL, nt);

    float* out = (float*)d_out;
    size_t per_t = (size_t)B * L * L;
    for (int t = 0; t < T; t++) {
        step_kernel<<<grid, 256, smem_bytes>>>(
            x, aW1, ab1, aW2, ab2, rW1, rb1, rW2, rb2,
            out + (size_t)t * per_t, t, B, L, nt);
        lmbd_step_kernel<<<(BL + 255) / 256, 256>>>(BL, nt, lW1, lb1, lW2, lb2, t);
    }
}

// round 7
// speedup vs baseline: 1.5696x; 1.5696x over previous
#include <cuda_runtime.h>

#define TS 64
#define TP 65   // padded smem row stride
#define SVAL 2.1972245773362196f   // log(9)

typedef unsigned long long ull;

// Scratch (device globals). Sized for B=8, L=1024, nt=16.
__device__ float g_uu[8 * 1024 * 1024];
__device__ float g_ah[8 * 1024 * 1024];
__device__ float g_rs0[8 * 1024 * 16];   // rowsum partials, double-buffered
__device__ float g_rs1[8 * 1024 * 16];
__device__ float g_lm0[8 * 1024];        // lmbd, double-buffered
__device__ float g_lm1[8 * 1024];

__device__ __forceinline__ float sigf(float v) { return 1.0f / (1.0f + __expf(-v)); }

__device__ __forceinline__ void u2uah(float uq, float& uu, float& ah) {
    uu = sigf(2.f * (uq - SVAL)) * uq;
    ah = sigf(uu) * sigf(2.f * (uu - SVAL));
}

__device__ __forceinline__ void decode_pair(int p, int nt, int& I, int& J) {
    int rem = p, rl = nt, i = 0;
    while (rem >= rl) { rem -= rl; rl--; i++; }
    I = i; J = i + rem;
}

// ---- packed f32x2 helpers (Blackwell FFMA2) ----
__device__ __forceinline__ ull pk(float a, float b) {
    ull r; asm("mov.b64 %0, {%1, %2};" : "=l"(r) : "f"(a), "f"(b)); return r;
}
__device__ __forceinline__ void upk(ull p, float& a, float& b) {
    asm("mov.b64 {%0, %1}, %2;" : "=f"(a), "=f"(b) : "l"(p));
}
__device__ __forceinline__ ull fma2(ull a, ull b, ull c) {
    ull d; asm("fma.rn.f32x2 %0, %1, %2, %3;" : "=l"(d) : "l"(a), "l"(b), "l"(c)); return d;
}
__device__ __forceinline__ ull relu2(ull x) {
    float a, b; upk(x, a, b);
    return pk(fmaxf(a, 0.f), fmaxf(b, 0.f));
}

// Packed dual-MLP: lane0 = a-net, lane1 = r-net. Same arithmetic order as the
// scalar version (fma chains), so results are bitwise identical to scalar.
__device__ __forceinline__ void mlp2pk(const ull* W1, const ull* B1, const ull* W2, ull B2,
                                       float f0, float f1, float f2,
                                       float& oA, float& oR) {
    ull f0p = pk(f0, f0), f1p = pk(f1, f1), f2p = pk(f2, f2);
    ull h0 = relu2(fma2(W1[0], f0p, fma2(W1[1], f1p, fma2(W1[2], f2p, B1[0]))));
    ull h1 = relu2(fma2(W1[3], f0p, fma2(W1[4], f1p, fma2(W1[5], f2p, B1[1]))));
    ull h2 = relu2(fma2(W1[6], f0p, fma2(W1[7], f1p, fma2(W1[8], f2p, B1[2]))));
    ull o = fma2(W2[0], h0, fma2(W2[1], h1, fma2(W2[2], h2, B2)));
    float a, r; upk(o, a, r);
    oA = fmaxf(a, 0.f); oR = fmaxf(r, 0.f);
}

// ---------------------------------------------------------------------------
// Init: uu = ss(u-S)*u ; a_hat = sig(uu)*ss(uu-S) ; partial rowsums of a0
// ---------------------------------------------------------------------------
__global__ void __launch_bounds__(256) init_kernel(
    const float* __restrict__ u, const float* __restrict__ x,
    int B, int L, int nt) {
    __shared__ float H1[TS * TP];
    __shared__ float H2[TS * TP];
    __shared__ float xs[2][4][TS];

    int I, J;
    decode_pair(blockIdx.x, nt, I, J);
    int b = blockIdx.y;
    bool diag = (I == J);
    int i0 = I * TS, j0 = J * TS;
    int tid = threadIdx.x, tx = tid & 15, ty = tid >> 4;
    size_t MN = (size_t)L * L;
    const float* Ub = u + (size_t)b * MN;
    float* uuB = g_uu + (size_t)b * MN;
    float* ahB = g_ah + (size_t)b * MN;

    if (tid < TS) {
        const float* xr = x + ((size_t)b * L + i0 + tid) * 4;
        xs[0][0][tid] = xr[0]; xs[0][1][tid] = xr[1]; xs[0][2][tid] = xr[2]; xs[0][3][tid] = xr[3];
        xr = x + ((size_t)b * L + j0 + tid) * 4;
        xs[1][0][tid] = xr[0]; xs[1][1][tid] = xr[1]; xs[1][2][tid] = xr[2]; xs[1][3][tid] = xr[3];
    }

#pragma unroll
    for (int it = 0; it < 4; it++) {
        int r = ty + 16 * it, c0 = 4 * tx;
        size_t off = (size_t)(i0 + r) * L + j0 + c0;
        float4 uv = *(const float4*)(Ub + off);
        float4 uo, ao;
        u2uah(uv.x, uo.x, ao.x); u2uah(uv.y, uo.y, ao.y);
        u2uah(uv.z, uo.z, ao.z); u2uah(uv.w, uo.w, ao.w);
        *(float4*)(uuB + off) = uo;
        *(float4*)(ahB + off) = ao;
        H1[r * TP + c0] = ao.x; H1[r * TP + c0 + 1] = ao.y;
        H1[r * TP + c0 + 2] = ao.z; H1[r * TP + c0 + 3] = ao.w;
        if (!diag) {
            size_t off2 = (size_t)(j0 + r) * L + i0 + c0;
            float4 uv2 = *(const float4*)(Ub + off2);
            float4 uo2, ao2;
            u2uah(uv2.x, uo2.x, ao2.x); u2uah(uv2.y, uo2.y, ao2.y);
            u2uah(uv2.z, uo2.z, ao2.z); u2uah(uv2.w, uo2.w, ao2.w);
            *(float4*)(uuB + off2) = uo2;
            *(float4*)(ahB + off2) = ao2;
            H2[r * TP + c0] = ao2.x; H2[r * TP + c0 + 1] = ao2.y;
            H2[r * TP + c0 + 2] = ao2.z; H2[r * TP + c0 + 3] = ao2.w;
        }
    }
    __syncthreads();

#pragma unroll
    for (int it = 0; it < 4; it++) {
        int r = ty + 16 * it, c0 = 4 * tx;
        {
            float p0 = xs[0][0][r], p1 = xs[0][1][r], p2 = xs[0][2][r], p3 = xs[0][3][r];
            float part = 0.f;
#pragma unroll
            for (int k = 0; k < 4; k++) {
                int c = c0 + k;
                float q0 = xs[1][0][c], q1 = xs[1][1][c], q2 = xs[1][2][c], q3 = xs[1][3][c];
                float mm = p0 * q1 + q0 * p1 + p2 * q3 + q2 * p3 + p1 * q3 + q1 * p3;
                float h1 = H1[r * TP + c];
                float h2 = diag ? H1[c * TP + r] : H2[c * TP + r];
                part += 0.5f * (h1 * h1 + h2 * h2) * mm;
            }
            part += __shfl_xor_sync(0xffffffffu, part, 8, 16);
            part += __shfl_xor_sync(0xffffffffu, part, 4, 16);
            part += __shfl_xor_sync(0xffffffffu, part, 2, 16);
            part += __shfl_xor_sync(0xffffffffu, part, 1, 16);
            if (tx == 0) g_rs0[((size_t)(b * L + i0 + r)) * nt + J] = part;
        }
        if (!diag) {
            float p0 = xs[1][0][r], p1 = xs[1][1][r], p2 = xs[1][2][r], p3 = xs[1][3][r];
            float part = 0.f;
#pragma unroll
            for (int k = 0; k < 4; k++) {
                int c = c0 + k;
                float q0 = xs[0][0][c], q1 = xs[0][1][c], q2 = xs[0][2][c], q3 = xs[0][3][c];
                float mm = p0 * q1 + q0 * p1 + p2 * q3 + q2 * p3 + p1 * q3 + q1 * p3;
                float h1 = H2[r * TP + c];
                float h2 = H1[c * TP + r];
                part += 0.5f * (h1 * h1 + h2 * h2) * mm;
            }
            part += __shfl_xor_sync(0xffffffffu, part, 8, 16);
            part += __shfl_xor_sync(0xffffffffu, part, 4, 16);
            part += __shfl_xor_sync(0xffffffffu, part, 2, 16);
            part += __shfl_xor_sync(0xffffffffu, part, 1, 16);
            if (tx == 0) g_rs0[((size_t)(b * L + j0 + r)) * nt + I] = part;
        }
    }
}

// ---------------------------------------------------------------------------
// One timestep, symmetric-pair formulation. Includes fused lambda prologue.
// Block covers tile pair (I,J)+(J,I). Each thread handles element pairs.
// ---------------------------------------------------------------------------
__global__ void __launch_bounds__(256, 3) step_kernel(
    const float* __restrict__ x,
    const float* __restrict__ aW1, const float* __restrict__ ab1,
    const float* __restrict__ aW2, const float* __restrict__ ab2,
    const float* __restrict__ rW1, const float* __restrict__ rb1,
    const float* __restrict__ rW2, const float* __restrict__ rb2,
    const float* __restrict__ lW1, const float* __restrict__ lb1,
    const float* __restrict__ lW2, const float* __restrict__ lb2,
    float* __restrict__ out, int t, int B, int L, int nt) {
    extern __shared__ float sm[];
    float* T0 = sm;                 // uu(J,I) transposed: T0[x*TP+y] = uu(j0+y, i0+x)
    float* T1 = sm + TS * TP;       // ah(J,I) transposed
    float* T2 = sm + 2 * TS * TP;   // ahn for (J,I) tile, exchange
    float* T3 = sm + 3 * TS * TP;   // a values, exchange
    __shared__ float xsI[4][TS];    // raw p for i-rows
    __shared__ float xsJ[4][TS];    // transformed q~ for j-rows
    __shared__ float gsm[2][TS];    // g = lmbd * ss(rowsum-1)

    int I, J;
    decode_pair(blockIdx.x, nt, I, J);
    int b = blockIdx.y;
    int i0 = I * TS, j0 = J * TS;
    int tid = threadIdx.x, tx = tid & 15, ty = tid >> 4;
    size_t MN = (size_t)L * L;
    const float* uuB = g_uu + (size_t)b * MN;
    float* ahB = g_ah + (size_t)b * MN;
    float* outB = out + (size_t)b * MN;

    const float* rs_rd = (t & 1) ? g_rs1 : g_rs0;
    float* rs_wr = (t & 1) ? g_rs0 : g_rs1;
    const float* lm_rd = (t & 1) ? g_lm0 : g_lm1;   // prev = buf[(t-1)&1]
    float* lm_wr = (t & 1) ? g_lm1 : g_lm0;         // cur  = buf[t&1]

    // ---- prologue: x feature vectors + lambda/g for this block's 128 rows ----
    if (tid < TS) {
        const float* xr = x + ((size_t)b * L + i0 + tid) * 4;
        xsI[0][tid] = xr[0]; xsI[1][tid] = xr[1]; xsI[2][tid] = xr[2]; xsI[3][tid] = xr[3];
    } else if (tid < 2 * TS) {
        int c = tid - TS;
        const float* xr = x + ((size_t)b * L + j0 + c) * 4;
        float q0 = xr[0], q1 = xr[1], q2 = xr[2], q3 = xr[3];
        // m = dot(p, (q1, q0+q3, q3, q2+q1))
        xsJ[0][c] = q1; xsJ[1][c] = q0 + q3; xsJ[2][c] = q3; xsJ[3][c] = q2 + q1;
    }
    if (tid < 2 * TS) {
        int side = tid >> 6, rr = tid & 63;
        int row = (side ? j0 : i0) + rr;
        int gidx = b * L + row;
        const float4* rp = (const float4*)(rs_rd + (size_t)gidx * nt);
        float4 s0 = rp[0], s1 = rp[1], s2 = rp[2], s3 = rp[3];
        float rs = ((s0.x + s0.y) + (s0.z + s0.w)) + ((s1.x + s1.y) + (s1.z + s1.w))
                 + ((s2.x + s2.y) + (s2.z + s2.w)) + ((s3.x + s3.y) + (s3.z + s3.w));
        float lm;
        if (t == 0) {
            lm = fmaxf(rs - 1.f, 0.f);
        } else {
            float lg = fmaxf(rs - 1.f, 0.f);
            float lp = lm_rd[gidx];
            const float* w1 = lW1 + (t - 1) * 6;
            const float* b1 = lb1 + (t - 1) * 3;
            const float* w2 = lW2 + (t - 1) * 3;
            float b2 = __ldg(lb2 + (t - 1));
            float h0 = fmaxf(__ldg(w1 + 0) * lp + __ldg(w1 + 1) * lg + __ldg(b1 + 0), 0.f);
            float h1 = fmaxf(__ldg(w1 + 2) * lp + __ldg(w1 + 3) * lg + __ldg(b1 + 1), 0.f);
            float h2 = fmaxf(__ldg(w1 + 4) * lp + __ldg(w1 + 5) * lg + __ldg(b1 + 2), 0.f);
            lm = fmaxf(__ldg(w2 + 0) * h0 + __ldg(w2 + 1) * h1 + __ldg(w2 + 2) * h2 + b2, 0.f);
        }
        lm_wr[gidx] = lm;                       // duplicate writes: identical bits
        gsm[side][rr] = lm * sigf(2.f * (rs - 1.f));
    }

    // ---- per-timestep MLP params as (a,r) lane pairs ----
    ull W1p[9], B1p[3], W2p[3], B2p;
    {
        const float* qa = aW1 + t * 9; const float* qr = rW1 + t * 9;
#pragma unroll
        for (int k = 0; k < 9; k++) W1p[k] = pk(__ldg(qa + k), __ldg(qr + k));
        const float* ba = ab1 + t * 3; const float* br = rb1 + t * 3;
        const float* va = aW2 + t * 3; const float* vr = rW2 + t * 3;
#pragma unroll
        for (int k = 0; k < 3; k++) {
            B1p[k] = pk(__ldg(ba + k), __ldg(br + k));
            W2p[k] = pk(__ldg(va + k), __ldg(vr + k));
        }
        B2p = pk(__ldg(ab2 + t), __ldg(rb2 + t));
    }

    // ---- Phase A: stage (J,I) tile of uu/ah transposed into smem ----
#pragma unroll
    for (int it = 0; it < 4; it++) {
        int jr = ty + 16 * it, c0 = 4 * tx;
        size_t off = (size_t)(j0 + jr) * L + i0 + c0;
        float4 uv = *(const float4*)(uuB + off);
        float4 av = *(const float4*)(ahB + off);
        T0[(c0 + 0) * TP + jr] = uv.x; T0[(c0 + 1) * TP + jr] = uv.y;
        T0[(c0 + 2) * TP + jr] = uv.z; T0[(c0 + 3) * TP + jr] = uv.w;
        T1[(c0 + 0) * TP + jr] = av.x; T1[(c0 + 1) * TP + jr] = av.y;
        T1[(c0 + 2) * TP + jr] = av.z; T1[(c0 + 3) * TP + jr] = av.w;
    }
    __syncthreads();

    // ---- Phase B: pair compute ----
#pragma unroll
    for (int it = 0; it < 4; it++) {
        int r = ty + 16 * it, c0 = 4 * tx;
        float p0 = xsI[0][r], p1 = xsI[1][r], p2 = xsI[2][r], p3 = xsI[3][r];
        float gi = gsm[0][r];
        size_t off = (size_t)(i0 + r) * L + j0 + c0;
        float4 uu4 = *(const float4*)(uuB + off);
        float4 ah4 = *(const float4*)(ahB + off);
        float uud[4] = {uu4.x, uu4.y, uu4.z, uu4.w};
        float ahd[4] = {ah4.x, ah4.y, ah4.z, ah4.w};
        float nv[4], av[4];
        float part = 0.f;
#pragma unroll
        for (int k = 0; k < 4; k++) {
            int c = c0 + k;
            float uut = T0[r * TP + c];
            float aht = T1[r * TP + c];
            float mm = fmaf(p0, xsJ[0][c], fmaf(p1, xsJ[1][c],
                       fmaf(p2, xsJ[2][c], p3 * xsJ[3][c])));
            float gs = (gi + gsm[1][c]) - 0.5f * (uud[k] + uut);
            float mg = mm * gs;
            float oA, oR;
            // direction (i,j)
            mlp2pk(W1p, B1p, W2p, B2p, ahd[k], ahd[k] * mg, uud[k], oA, oR);
            float ahn_ij = fminf(fmaxf(oA - oR, 0.f), 1.f);
            // direction (j,i)
            mlp2pk(W1p, B1p, W2p, B2p, aht, aht * mg, uut, oA, oR);
            float ahn_ji = fminf(fmaxf(oA - oR, 0.f), 1.f);
            float aa = 0.5f * (ahn_ij * ahn_ij + ahn_ji * ahn_ji) * mm;
            nv[k] = ahn_ij;
            av[k] = aa;
            part += aa;
            T2[c * TP + r] = ahn_ji;
            T3[c * TP + r] = aa;
        }
        *(float4*)(ahB + off) = make_float4(nv[0], nv[1], nv[2], nv[3]);
        __stcs((float4*)(outB + off), make_float4(av[0], av[1], av[2], av[3]));
        part += __shfl_xor_sync(0xffffffffu, part, 8, 16);
        part += __shfl_xor_sync(0xffffffffu, part, 4, 16);
        part += __shfl_xor_sync(0xffffffffu, part, 2, 16);
        part += __shfl_xor_sync(0xffffffffu, part, 1, 16);
        if (tx == 0) rs_wr[((size_t)(b * L + i0 + r)) * nt + J] = part;
    }
    __syncthreads();

    // ---- Phase C: coalesced writeback of the (J,I) tile + row-j partials ----
#pragma unroll
    for (int it = 0; it < 4; it++) {
        int r = ty + 16 * it, c0 = 4 * tx;
        size_t off = (size_t)(j0 + r) * L + i0 + c0;
        float4 nh = make_float4(T2[r * TP + c0], T2[r * TP + c0 + 1],
                                T2[r * TP + c0 + 2], T2[r * TP + c0 + 3]);
        *(float4*)(ahB + off) = nh;
        float a0 = T3[r * TP + c0], a1 = T3[r * TP + c0 + 1];
        float a2 = T3[r * TP + c0 + 2], a3 = T3[r * TP + c0 + 3];
        __stcs((float4*)(outB + off), make_float4(a0, a1, a2, a3));
        float part = ((a0 + a1) + (a2 + a3));
        part += __shfl_xor_sync(0xffffffffu, part, 8, 16);
        part += __shfl_xor_sync(0xffffffffu, part, 4, 16);
        part += __shfl_xor_sync(0xffffffffu, part, 2, 16);
        part += __shfl_xor_sync(0xffffffffu, part, 1, 16);
        if (tx == 0) rs_wr[((size_t)(b * L + j0 + r)) * nt + I] = part;
    }
}

// ---------------------------------------------------------------------------
extern "C" void kernel_launch(void* const* d_in, const int* in_sizes, int n_in,
                              void* d_out, int out_size) {
    const float* u   = (const float*)d_in[0];
    const float* x   = (const float*)d_in[1];
    const float* aW1 = (const float*)d_in[3];
    const float* ab1 = (const float*)d_in[4];
    const float* aW2 = (const float*)d_in[5];
    const float* ab2 = (const float*)d_in[6];
    const float* rW1 = (const float*)d_in[7];
    const float* rb1 = (const float*)d_in[8];
    const float* rW2 = (const float*)d_in[9];
    const float* rb2 = (const float*)d_in[10];
    const float* lW1 = (const float*)d_in[11];
    const float* lb1 = (const float*)d_in[12];
    const float* lW2 = (const float*)d_in[13];
    const float* lb2 = (const float*)d_in[14];

    long long BLL = in_sizes[0];            // B*L*L
    long long BL4 = in_sizes[1];            // B*L*4
    int L = (int)(BLL * 4 / BL4);
    int B = (int)(BL4 / (4LL * L));
    int T = (int)((long long)out_size / BLL);
    int nt = L / TS;
    int npairs = nt * (nt + 1) / 2;

    const int smem_bytes = 4 * TS * TP * (int)sizeof(float);   // 66,560 B
    cudaFuncSetAttribute(step_kernel,
                         cudaFuncAttributeMaxDynamicSharedMemorySize, smem_bytes);

    dim3 grid(npairs, B);
    init_kernel<<<grid, 256>>>(u, x, B, L, nt);

    float* out = (float*)d_out;
    size_t per_t = (size_t)B * L * L;
    for (int t = 0; t < T; t++) {
        step_kernel<<<grid, 256, smem_bytes>>>(
            x, aW1, ab1, aW2, ab2, rW1, rb1, rW2, rb2,
            lW1, lb1, lW2, lb2,
            out + (size_t)t * per_t, t, B, L, nt);
    }
}